// round 1
// baseline (speedup 1.0000x reference)
#include <cuda_runtime.h>
#include <math.h>

#define N_NODES 100000
#define N_EDGES 1600000
#define HID 64

// Scratch (no cudaMalloc allowed) — ~51.6 MB of device globals.
__device__ float        g_h[N_NODES * HID];
__device__ float        g_agg[N_NODES * HID];
__device__ unsigned int g_deg[N_NODES];

// ---------------------------------------------------------------------------
// Kernel 0: zero the accumulation buffers (must be re-zeroed every replay).
// ---------------------------------------------------------------------------
__global__ void zero_kernel() {
    int i      = blockIdx.x * blockDim.x + threadIdx.x;
    int stride = gridDim.x * blockDim.x;
    for (int k = i; k < N_NODES * HID; k += stride) g_agg[k] = 0.0f;
    for (int k = i; k < N_NODES; k += stride)       g_deg[k] = 0u;
}

// ---------------------------------------------------------------------------
// Kernel 1: h = feat @ W_in + b_in   (100000x64 @ 64x64)
// 64 nodes per 256-thread block; W_in and the feat tile staged in smem.
// ---------------------------------------------------------------------------
__global__ void input_gemm_kernel(const float* __restrict__ feat,
                                  const float* __restrict__ W_in,
                                  const float* __restrict__ b_in) {
    __shared__ float sW[HID * HID];   // 16 KB
    __shared__ float sB[HID];
    __shared__ float sF[64][HID];     // 16 KB

    int tid   = threadIdx.x;
    int node0 = blockIdx.x * 64;

    for (int k = tid; k < HID * HID; k += 256) sW[k] = W_in[k];
    if (tid < HID) sB[tid] = b_in[tid];
    for (int k = tid; k < 64 * HID; k += 256) {
        int n  = k >> 6;
        int gn = node0 + n;
        sF[n][k & 63] = (gn < N_NODES) ? feat[gn * HID + (k & 63)] : 0.0f;
    }
    __syncthreads();

    for (int o = tid; o < 64 * HID; o += 256) {
        int n  = o >> 6;
        int j  = o & 63;
        int gn = node0 + n;
        if (gn >= N_NODES) continue;
        float acc = sB[j];
#pragma unroll
        for (int k = 0; k < HID; k++)
            acc = fmaf(sF[n][k], sW[k * HID + j], acc);
        g_h[gn * HID + j] = acc;
    }
}

// ---------------------------------------------------------------------------
// Kernel 2: per-edge gate + message scatter.
// One warp per edge; lane i owns features [2i, 2i+1] (float2, coalesced).
//   w = sigmoid(hu.W_u + hv.W_v + b_edge);  agg[dst] += hu * w;  deg[dst]++
// ---------------------------------------------------------------------------
__global__ void edge_kernel(const int* __restrict__ src,
                            const int* __restrict__ dst,
                            const float* __restrict__ W_edge,
                            const float* __restrict__ b_edge) {
    int lane = threadIdx.x & 31;
    long long e = (long long)(blockIdx.x * blockDim.x + threadIdx.x) >> 5;
    if (e >= N_EDGES) return;

    int s = src[e];
    int d = dst[e];

    const float2* h2 = (const float2*)g_h;
    float2 hu = h2[(long long)s * 32 + lane];
    float2 hv = h2[(long long)d * 32 + lane];

    float2 wu = ((const float2*)W_edge)[lane];        // W_edge[0:64]
    float2 wv = ((const float2*)W_edge)[32 + lane];   // W_edge[64:128]

    float p = hu.x * wu.x + hu.y * wu.y + hv.x * wv.x + hv.y * wv.y;
#pragma unroll
    for (int off = 16; off; off >>= 1)
        p += __shfl_xor_sync(0xffffffffu, p, off);

    float w = 1.0f / (1.0f + __expf(-(p + b_edge[0])));

    float* aggRow = &g_agg[(long long)d * HID + 2 * lane];
    atomicAdd(aggRow,     hu.x * w);
    atomicAdd(aggRow + 1, hu.y * w);
    if (lane == 0) atomicAdd(&g_deg[d], 1u);
}

// ---------------------------------------------------------------------------
// Kernel 3: h_new = (deg > 0) ? agg : h;  out = h_new @ W_out + b_out.
// One warp per node; lane i owns features [2i, 2i+1].
// W_out row-major [64][2] -> float4 per lane covers rows 2i and 2i+1.
// ---------------------------------------------------------------------------
__global__ void out_kernel(const float* __restrict__ W_out,
                           const float* __restrict__ b_out,
                           float* __restrict__ out) {
    int lane = threadIdx.x & 31;
    long long n = (long long)(blockIdx.x * blockDim.x + threadIdx.x) >> 5;
    if (n >= N_NODES) return;

    bool useAgg = g_deg[n] > 0u;
    const float2* src2 = (const float2*)(useAgg ? g_agg : g_h);
    float2 v = src2[n * 32 + lane];

    float4 w4 = ((const float4*)W_out)[lane];
    // w4 = { W[2i][0], W[2i][1], W[2i+1][0], W[2i+1][1] }
    float s0 = v.x * w4.x + v.y * w4.z;
    float s1 = v.x * w4.y + v.y * w4.w;
#pragma unroll
    for (int off = 16; off; off >>= 1) {
        s0 += __shfl_xor_sync(0xffffffffu, s0, off);
        s1 += __shfl_xor_sync(0xffffffffu, s1, off);
    }
    if (lane == 0) {
        out[n * 2 + 0] = s0 + b_out[0];
        out[n * 2 + 1] = s1 + b_out[1];
    }
}

// ---------------------------------------------------------------------------
extern "C" void kernel_launch(void* const* d_in, const int* in_sizes, int n_in,
                              void* d_out, int out_size) {
    const float* feat   = (const float*)d_in[0];
    const int*   src    = (const int*)  d_in[1];
    const int*   dst    = (const int*)  d_in[2];
    const float* W_in   = (const float*)d_in[3];
    const float* b_in   = (const float*)d_in[4];
    const float* W_edge = (const float*)d_in[5];
    const float* b_edge = (const float*)d_in[6];
    const float* W_out  = (const float*)d_in[7];
    const float* b_out  = (const float*)d_in[8];
    float* out = (float*)d_out;

    zero_kernel<<<1024, 256>>>();
    input_gemm_kernel<<<(N_NODES + 63) / 64, 256>>>(feat, W_in, b_in);
    // one warp per edge: N_EDGES * 32 threads
    edge_kernel<<<(N_EDGES * 32 + 255) / 256, 256>>>(src, dst, W_edge, b_edge);
    out_kernel<<<(int)((N_NODES * 32LL + 255) / 256), 256>>>(W_out, b_out, out);
}

// round 2
// speedup vs baseline: 1.4817x; 1.4817x over previous
#include <cuda_runtime.h>
#include <math.h>

#define N_NODES 100000
#define N_EDGES 1600000
#define HID 64

// Scratch (no cudaMalloc allowed).
__device__ float        g_h[N_NODES * HID];
__device__ float        g_agg[N_NODES * HID];
__device__ float        g_dotu[N_NODES];
__device__ float        g_dotv[N_NODES];
__device__ unsigned int g_deg[N_NODES];

// ---------------------------------------------------------------------------
// Kernel 0: zero accumulators (re-zeroed every replay; float4 stores).
// ---------------------------------------------------------------------------
__global__ void zero_kernel() {
    int i      = blockIdx.x * blockDim.x + threadIdx.x;
    int stride = gridDim.x * blockDim.x;
    float4* a4 = (float4*)g_agg;
    const int n4 = N_NODES * HID / 4;
    for (int k = i; k < n4; k += stride) a4[k] = make_float4(0.f, 0.f, 0.f, 0.f);
    for (int k = i; k < N_NODES; k += stride) g_deg[k] = 0u;
}

// ---------------------------------------------------------------------------
// Kernel 1: h = feat @ W_in + b_in, fused with per-node gate dot products
//   dotu[n] = h[n]·W_edge[0:64],  dotv[n] = h[n]·W_edge[64:128]
// 64 nodes per 256-thread block.
// ---------------------------------------------------------------------------
__global__ void input_gemm_kernel(const float* __restrict__ feat,
                                  const float* __restrict__ W_in,
                                  const float* __restrict__ b_in,
                                  const float* __restrict__ W_edge) {
    __shared__ float sW[HID * HID];     // 16 KB
    __shared__ float sB[HID];
    __shared__ float sF[64][HID];       // 16 KB
    __shared__ float sH[64][HID + 1];   // 16.25 KB (padded: conflict-free cols)
    __shared__ float sWu[HID], sWv[HID];

    int tid   = threadIdx.x;
    int node0 = blockIdx.x * 64;

    for (int k = tid; k < HID * HID; k += 256) sW[k] = W_in[k];
    if (tid < HID) {
        sB[tid]  = b_in[tid];
        sWu[tid] = W_edge[tid];
        sWv[tid] = W_edge[HID + tid];
    }
    for (int k = tid; k < 64 * HID; k += 256) {
        int n  = k >> 6;
        int gn = node0 + n;
        sF[n][k & 63] = (gn < N_NODES) ? feat[gn * HID + (k & 63)] : 0.0f;
    }
    __syncthreads();

    for (int o = tid; o < 64 * HID; o += 256) {
        int n  = o >> 6;
        int j  = o & 63;
        int gn = node0 + n;
        float acc = sB[j];
#pragma unroll
        for (int k = 0; k < HID; k++)
            acc = fmaf(sF[n][k], sW[k * HID + j], acc);
        sH[n][j] = acc;
        if (gn < N_NODES) g_h[gn * HID + j] = acc;
    }
    __syncthreads();

    if (tid < 64) {
        int gn = node0 + tid;
        if (gn < N_NODES) {
            float du = 0.f, dv = 0.f;
#pragma unroll
            for (int j = 0; j < HID; j++) {
                float hv = sH[tid][j];
                du = fmaf(hv, sWu[j], du);
                dv = fmaf(hv, sWv[j], dv);
            }
            g_dotu[gn] = du;
            g_dotv[gn] = dv;
        }
    }
}

// ---------------------------------------------------------------------------
// Kernel 2: edge gate + scatter. 16 lanes per edge, lane owns one float4.
//   w = sigmoid(dotu[s] + dotv[d] + b);  agg[d] += h[s] * w (float4 RED);
//   deg[d]++ (one lane).
// ---------------------------------------------------------------------------
__global__ void edge_kernel(const int* __restrict__ src,
                            const int* __restrict__ dst,
                            const float* __restrict__ b_edge) {
    long long t = (long long)blockIdx.x * blockDim.x + threadIdx.x;
    long long e = t >> 4;
    int c = (int)(t & 15);
    if (e >= N_EDGES) return;

    int s = src[e];
    int d = dst[e];

    float w = 0.f;
    if (c == 0) {
        float p = g_dotu[s] + g_dotv[d] + b_edge[0];
        w = 1.0f / (1.0f + __expf(-p));
        atomicAdd(&g_deg[d], 1u);
    }
    int lane = threadIdx.x & 31;
    w = __shfl_sync(0xffffffffu, w, lane & 16);   // broadcast within half-warp

    float4 v = ((const float4*)g_h)[(long long)s * 16 + c];
    float4 m = make_float4(v.x * w, v.y * w, v.z * w, v.w * w);
    atomicAdd((float4*)&g_agg[(long long)d * HID + c * 4], m);
}

// ---------------------------------------------------------------------------
// Kernel 3: h_new = (deg > 0) ? agg : h;  out = h_new @ W_out + b_out.
// One warp per node; lane i owns features [2i, 2i+1].
// ---------------------------------------------------------------------------
__global__ void out_kernel(const float* __restrict__ W_out,
                           const float* __restrict__ b_out,
                           float* __restrict__ out) {
    int lane = threadIdx.x & 31;
    long long n = (long long)(blockIdx.x * blockDim.x + threadIdx.x) >> 5;
    if (n >= N_NODES) return;

    bool useAgg = g_deg[n] > 0u;
    const float2* src2 = (const float2*)(useAgg ? g_agg : g_h);
    float2 v = src2[n * 32 + lane];

    float4 w4 = ((const float4*)W_out)[lane];
    float s0 = v.x * w4.x + v.y * w4.z;
    float s1 = v.x * w4.y + v.y * w4.w;
#pragma unroll
    for (int off = 16; off; off >>= 1) {
        s0 += __shfl_xor_sync(0xffffffffu, s0, off);
        s1 += __shfl_xor_sync(0xffffffffu, s1, off);
    }
    if (lane == 0) {
        out[n * 2 + 0] = s0 + b_out[0];
        out[n * 2 + 1] = s1 + b_out[1];
    }
}

// ---------------------------------------------------------------------------
extern "C" void kernel_launch(void* const* d_in, const int* in_sizes, int n_in,
                              void* d_out, int out_size) {
    const float* feat   = (const float*)d_in[0];
    const int*   src    = (const int*)  d_in[1];
    const int*   dst    = (const int*)  d_in[2];
    const float* W_in   = (const float*)d_in[3];
    const float* b_in   = (const float*)d_in[4];
    const float* W_edge = (const float*)d_in[5];
    const float* b_edge = (const float*)d_in[6];
    const float* W_out  = (const float*)d_in[7];
    const float* b_out  = (const float*)d_in[8];
    float* out = (float*)d_out;

    zero_kernel<<<2048, 256>>>();
    input_gemm_kernel<<<(N_NODES + 63) / 64, 256>>>(feat, W_in, b_in, W_edge);
    edge_kernel<<<(int)((N_EDGES * 16LL + 255) / 256), 256>>>(src, dst, b_edge);
    out_kernel<<<(int)((N_NODES * 32LL + 255) / 256), 256>>>(W_out, b_out, out);
}

// round 3
// speedup vs baseline: 1.8293x; 1.2346x over previous
#include <cuda_runtime.h>
#include <math.h>

#define N_NODES 100000
#define N_EDGES 1600000
#define HID 64
#define SCAN_BLK 512
#define N_SCAN_BLOCKS ((N_NODES + SCAN_BLK - 1) / SCAN_BLK)   // 196

// Scratch (no cudaMalloc allowed).
__device__ float g_h[N_NODES * HID];        // 25.6 MB
__device__ float g_dotu[N_NODES];
__device__ float g_dotv[N_NODES];
__device__ int   g_cnt[N_NODES];            // per-dst edge count
__device__ int   g_off[N_NODES];            // exclusive offsets
__device__ int   g_fill[N_NODES];           // scatter cursors
__device__ int   g_bsum[N_SCAN_BLOCKS];
__device__ int   g_srcSorted[N_EDGES];      // 6.4 MB

// ---------------------------------------------------------------------------
// K0: zero histogram counters (re-zeroed every replay).
// ---------------------------------------------------------------------------
__global__ void zero_kernel() {
    int i = blockIdx.x * blockDim.x + threadIdx.x;
    if (i < N_NODES) g_cnt[i] = 0;
}

// ---------------------------------------------------------------------------
// K1: h = feat @ W_in + b_in, fused with per-node gate dot products.
// ---------------------------------------------------------------------------
__global__ void input_gemm_kernel(const float* __restrict__ feat,
                                  const float* __restrict__ W_in,
                                  const float* __restrict__ b_in,
                                  const float* __restrict__ W_edge) {
    __shared__ float sW[HID * HID];
    __shared__ float sB[HID];
    __shared__ float sF[64][HID];
    __shared__ float sH[64][HID + 1];
    __shared__ float sWu[HID], sWv[HID];

    int tid   = threadIdx.x;
    int node0 = blockIdx.x * 64;

    for (int k = tid; k < HID * HID; k += 256) sW[k] = W_in[k];
    if (tid < HID) {
        sB[tid]  = b_in[tid];
        sWu[tid] = W_edge[tid];
        sWv[tid] = W_edge[HID + tid];
    }
    for (int k = tid; k < 64 * HID; k += 256) {
        int n  = k >> 6;
        int gn = node0 + n;
        sF[n][k & 63] = (gn < N_NODES) ? feat[gn * HID + (k & 63)] : 0.0f;
    }
    __syncthreads();

    for (int o = tid; o < 64 * HID; o += 256) {
        int n  = o >> 6;
        int j  = o & 63;
        int gn = node0 + n;
        float acc = sB[j];
#pragma unroll
        for (int k = 0; k < HID; k++)
            acc = fmaf(sF[n][k], sW[k * HID + j], acc);
        sH[n][j] = acc;
        if (gn < N_NODES) g_h[gn * HID + j] = acc;
    }
    __syncthreads();

    if (tid < 64) {
        int gn = node0 + tid;
        if (gn < N_NODES) {
            float du = 0.f, dv = 0.f;
#pragma unroll
            for (int j = 0; j < HID; j++) {
                float hv = sH[tid][j];
                du = fmaf(hv, sWu[j], du);
                dv = fmaf(hv, sWv[j], dv);
            }
            g_dotu[gn] = du;
            g_dotv[gn] = dv;
        }
    }
}

// ---------------------------------------------------------------------------
// K2: histogram of dst.
// ---------------------------------------------------------------------------
__global__ void hist_kernel(const int* __restrict__ dst) {
    int e = blockIdx.x * blockDim.x + threadIdx.x;
    if (e < N_EDGES) atomicAdd(&g_cnt[dst[e]], 1);
}

// ---------------------------------------------------------------------------
// K3a: per-block partial sums of counts.
// ---------------------------------------------------------------------------
__global__ void scan_bsum_kernel() {
    __shared__ int sS[SCAN_BLK];
    int tid = threadIdx.x;
    int i   = blockIdx.x * SCAN_BLK + tid;
    sS[tid] = (i < N_NODES) ? g_cnt[i] : 0;
    __syncthreads();
    for (int off = SCAN_BLK / 2; off > 0; off >>= 1) {
        if (tid < off) sS[tid] += sS[tid + off];
        __syncthreads();
    }
    if (tid == 0) g_bsum[blockIdx.x] = sS[0];
}

// K3b: serial exclusive scan of 196 block sums (trivial).
__global__ void scan_boff_kernel() {
    if (threadIdx.x == 0) {
        int run = 0;
        for (int b = 0; b < N_SCAN_BLOCKS; b++) {
            int v = g_bsum[b];
            g_bsum[b] = run;
            run += v;
        }
    }
}

// K3c: per-block exclusive scan + block offset -> g_off, g_fill.
__global__ void scan_final_kernel() {
    __shared__ int sS[SCAN_BLK];
    int tid = threadIdx.x;
    int i   = blockIdx.x * SCAN_BLK + tid;
    int v   = (i < N_NODES) ? g_cnt[i] : 0;
    sS[tid] = v;
    __syncthreads();
    // Hillis-Steele inclusive scan
    for (int off = 1; off < SCAN_BLK; off <<= 1) {
        int t = (tid >= off) ? sS[tid - off] : 0;
        __syncthreads();
        sS[tid] += t;
        __syncthreads();
    }
    if (i < N_NODES) {
        int excl = sS[tid] - v + g_bsum[blockIdx.x];
        g_off[i]  = excl;
        g_fill[i] = excl;
    }
}

// ---------------------------------------------------------------------------
// K4: scatter src indices into dst-sorted order.
// ---------------------------------------------------------------------------
__global__ void scatter_kernel(const int* __restrict__ src,
                               const int* __restrict__ dst) {
    int e = blockIdx.x * blockDim.x + threadIdx.x;
    if (e < N_EDGES) {
        int pos = atomicAdd(&g_fill[dst[e]], 1);
        g_srcSorted[pos] = src[e];
    }
}

// ---------------------------------------------------------------------------
// K5: atomic-free aggregate + fused output projection.
// One warp per node; two 16-lane halves process alternating edges.
// ---------------------------------------------------------------------------
__global__ void agg_out_kernel(const float* __restrict__ W_out,
                               const float* __restrict__ b_out,
                               const float* __restrict__ b_edge,
                               float* __restrict__ out) {
    int lane = threadIdx.x & 31;
    long long n = (long long)(blockIdx.x * blockDim.x + threadIdx.x) >> 5;
    if (n >= N_NODES) return;

    int c    = lane & 15;
    int half = lane >> 4;

    int start = g_off[n];
    int cnt   = g_cnt[n];
    float dv  = g_dotv[n];
    float be  = b_edge[0];

    float4 acc = make_float4(0.f, 0.f, 0.f, 0.f);
    const float4* h4 = (const float4*)g_h;

    for (int i = start + half; i < start + cnt; i += 2) {
        int s = g_srcSorted[i];                      // broadcast within half
        float p = g_dotu[s] + dv + be;
        float w = 1.0f / (1.0f + __expf(-p));
        float4 v = h4[(long long)s * 16 + c];
        acc.x = fmaf(v.x, w, acc.x);
        acc.y = fmaf(v.y, w, acc.y);
        acc.z = fmaf(v.z, w, acc.z);
        acc.w = fmaf(v.w, w, acc.w);
    }
    // combine the two halves
    acc.x += __shfl_xor_sync(0xffffffffu, acc.x, 16);
    acc.y += __shfl_xor_sync(0xffffffffu, acc.y, 16);
    acc.z += __shfl_xor_sync(0xffffffffu, acc.z, 16);
    acc.w += __shfl_xor_sync(0xffffffffu, acc.w, 16);

    if (cnt == 0) acc = h4[n * 16 + c];              // h_new = h when deg==0

    // out = h_new @ W_out + b_out; lane c owns features 4c..4c+3
    float4 wa = ((const float4*)W_out)[2 * c];       // rows 4c, 4c+1
    float4 wb = ((const float4*)W_out)[2 * c + 1];   // rows 4c+2, 4c+3
    float s0 = acc.x * wa.x + acc.y * wa.z + acc.z * wb.x + acc.w * wb.z;
    float s1 = acc.x * wa.y + acc.y * wa.w + acc.z * wb.y + acc.w * wb.w;
#pragma unroll
    for (int off = 8; off; off >>= 1) {
        s0 += __shfl_xor_sync(0xffffffffu, s0, off);
        s1 += __shfl_xor_sync(0xffffffffu, s1, off);
    }
    if (lane == 0) {
        out[n * 2 + 0] = s0 + b_out[0];
        out[n * 2 + 1] = s1 + b_out[1];
    }
}

// ---------------------------------------------------------------------------
extern "C" void kernel_launch(void* const* d_in, const int* in_sizes, int n_in,
                              void* d_out, int out_size) {
    const float* feat   = (const float*)d_in[0];
    const int*   src    = (const int*)  d_in[1];
    const int*   dst    = (const int*)  d_in[2];
    const float* W_in   = (const float*)d_in[3];
    const float* b_in   = (const float*)d_in[4];
    const float* W_edge = (const float*)d_in[5];
    const float* b_edge = (const float*)d_in[6];
    const float* W_out  = (const float*)d_in[7];
    const float* b_out  = (const float*)d_in[8];
    float* out = (float*)d_out;

    zero_kernel<<<(N_NODES + 255) / 256, 256>>>();
    input_gemm_kernel<<<(N_NODES + 63) / 64, 256>>>(feat, W_in, b_in, W_edge);
    hist_kernel<<<(N_EDGES + 255) / 256, 256>>>(dst);
    scan_bsum_kernel<<<N_SCAN_BLOCKS, SCAN_BLK>>>();
    scan_boff_kernel<<<1, 32>>>();
    scan_final_kernel<<<N_SCAN_BLOCKS, SCAN_BLK>>>();
    scatter_kernel<<<(N_EDGES + 255) / 256, 256>>>(src, dst);
    agg_out_kernel<<<(int)((N_NODES * 32LL + 255) / 256), 256>>>(W_out, b_out, b_edge, out);
}